// round 16
// baseline (speedup 1.0000x reference)
#include <cuda_runtime.h>
#include <cstdint>

#define NODES 20000
#define BATCH 32
#define FEAT  64
#define EIG   16
#define NOUT  64

// k1: 80 chunks x 250 nodes x 16 batch-pairs = 1280 blocks of 128 thr.
// 5 panels of 50 nodes per chunk (exact: 80*250 = 20000, 250 = 5*50).
#define NCHUNK 80
#define CH1    250
#define PN     50
#define NPAN   5
#define XS_B   3200          // floats per x panel (50*64)
#define VS_OFF 6400          // vs offset in floats (2*3200)
#define SM1    7200          // total smem floats = 28.8 KB

// k3: 157 tiles x 128 nodes (last tile 32), 16 batch-pairs
#define TN3    128
#define NBLK3  157

typedef unsigned long long ull;

// Scratch (static device globals: allocation-free per harness rules)
// g_zpart[c][bp][bb][i][f]: 80*16*2*1024 floats = 10.5 MB
__device__ float g_zpart[(size_t)NCHUNK * 16 * 2048];
__device__ float g_z[BATCH * FEAT * EIG];                      // 128 KB
__device__ float g_w[BATCH * NOUT * EIG];                      // 128 KB

// ---- packed fp32x2 helpers (full-rate fp32 on sm_103a goes through FFMA2) ----
__device__ __forceinline__ ull pack2(float lo, float hi) {
    ull r; asm("mov.b64 %0, {%1, %2};" : "=l"(r) : "f"(lo), "f"(hi)); return r;
}
__device__ __forceinline__ float2 unpack2(ull v) {
    float2 r; asm("mov.b64 {%0, %1}, %2;" : "=f"(r.x), "=f"(r.y) : "l"(v)); return r;
}
__device__ __forceinline__ ull ffma2(ull a, ull b, ull c) {
    ull d; asm("fma.rn.f32x2 %0, %1, %2, %3;" : "=l"(d) : "l"(a), "l"(b), "l"(c)); return d;
}

// ============================================================================
// Stage 1: z[b,i,f] = sum_m V[m,f] * x[b,m,i]
// R4's measured-best skeleton (simple smem staging, no pipeline, small
// blocks, high occupancy) + k3's MEASURED batch-pair V amortization:
// block = (250-node chunk, batch-PAIR), 128 thr = 4 fq-warps. Each warp
// walks all panel nodes for BOTH batches: per node 2x LDS.64 (x, lane-
// distinct) + 1 uniform LDS.128 (V, shared by both batches) + 8 FFMA2.
// Crossbar: 16 cyc/node-batch vs R4's 24 (V broadcast halved). ~60 regs +
// 28.8 KB smem -> ~7 blocks/SM = 28 warps (R12-15 ran at 16).
// Epilogue: R4-style DIRECT write (accumulators complete per warp; no
// cross-warp reduction -- the component that caused the R10/R13 failures).
// ============================================================================
__global__ __launch_bounds__(128)
void k1_project(const float* __restrict__ x, const float* __restrict__ V) {
    __shared__ __align__(16) float sm[SM1];   // xsA | xsB | vs
    const int c  = blockIdx.x;          // chunk 0..79
    const int bp = blockIdx.y;          // batch pair 0..15
    const int b0 = bp * 2;
    const int m0 = c * CH1;
    const int tid = threadIdx.x;
    const int fq = tid >> 5;            // warp = f-quad 0..3
    const int lane = tid & 31;          // lane = i-pair

    const float* xA0 = x + ((size_t)b0 * NODES) * FEAT;
    const float* xB0 = xA0 + (size_t)NODES * FEAT;

    ull aA0 = 0, aA1 = 0, aA2 = 0, aA3 = 0;
    ull aB0 = 0, aB1 = 0, aB2 = 0, aB3 = 0;

    for (int p = 0; p < NPAN; p++) {
        const int mp = m0 + p * PN;
        // cooperative load: xA (800 f4), xB (800 f4), V (200 f4)
        {
            const float4* sA = (const float4*)(xA0 + (size_t)mp * FEAT);
            const float4* sB = (const float4*)(xB0 + (size_t)mp * FEAT);
            const float4* sV = (const float4*)(V + (size_t)mp * EIG);
            float4* dA = (float4*)sm;
            float4* dB = (float4*)(sm + XS_B);
            float4* dV = (float4*)(sm + VS_OFF);
            for (int idx = tid; idx < 800; idx += 128) {
                dA[idx] = sA[idx];
                dB[idx] = sB[idx];
            }
            for (int idx = tid; idx < 200; idx += 128) dV[idx] = sV[idx];
        }
        __syncthreads();

        #pragma unroll 2
        for (int n = 0; n < PN; n++) {
            float2 xa = *(const float2*)(sm + n * FEAT + 2 * lane);
            float2 xb = *(const float2*)(sm + XS_B + n * FEAT + 2 * lane);
            ulonglong2 v = *(const ulonglong2*)(sm + VS_OFF + n * EIG + fq * 4);
            ull xa0 = pack2(xa.x, xa.x), xa1 = pack2(xa.y, xa.y);
            ull xb0 = pack2(xb.x, xb.x), xb1 = pack2(xb.y, xb.y);
            aA0 = ffma2(xa0, v.x, aA0);
            aA1 = ffma2(xa0, v.y, aA1);
            aA2 = ffma2(xa1, v.x, aA2);
            aA3 = ffma2(xa1, v.y, aA3);
            aB0 = ffma2(xb0, v.x, aB0);
            aB1 = ffma2(xb0, v.y, aB1);
            aB2 = ffma2(xb1, v.x, aB2);
            aB3 = ffma2(xb1, v.y, aB3);
        }
        __syncthreads();
    }

    // direct-write epilogue: g_zpart[c][bp][bb][i][f]
    {
        float* gz = g_zpart + ((size_t)c * 16 + bp) * 2048;
        float2 u0, u1;
        u0 = unpack2(aA0); u1 = unpack2(aA1);
        *(float4*)(gz + (2 * lane) * EIG + fq * 4)            = make_float4(u0.x, u0.y, u1.x, u1.y);
        u0 = unpack2(aA2); u1 = unpack2(aA3);
        *(float4*)(gz + (2 * lane + 1) * EIG + fq * 4)        = make_float4(u0.x, u0.y, u1.x, u1.y);
        u0 = unpack2(aB0); u1 = unpack2(aB1);
        *(float4*)(gz + 1024 + (2 * lane) * EIG + fq * 4)     = make_float4(u0.x, u0.y, u1.x, u1.y);
        u0 = unpack2(aB2); u1 = unpack2(aB3);
        *(float4*)(gz + 1024 + (2 * lane + 1) * EIG + fq * 4) = make_float4(u0.x, u0.y, u1.x, u1.y);
    }
}

// ============================================================================
// Stage 1b: reduce partial z over 80 chunks (fixed order -> deterministic)
// g_zpart inner layout [bp][bb][i][f] == g_z's [b][i][f] ordering.
// ============================================================================
__global__ __launch_bounds__(256)
void k1_reduce() {
    const int q = blockIdx.x * 256 + threadIdx.x;   // over 8192 float4
    const float4* zp = (const float4*)g_zpart;
    float4 s = make_float4(0.f, 0.f, 0.f, 0.f);
    #pragma unroll 8
    for (int c = 0; c < NCHUNK; c++) {
        float4 v = zp[(size_t)c * 8192 + q];
        s.x += v.x; s.y += v.y; s.z += v.z; s.w += v.w;
    }
    ((float4*)g_z)[q] = s;
}

// ============================================================================
// Stage 2: w[b,j,e] = sum_{i,f} G[j,i,e,f] * z[b,i,f]  (R12 verbatim)
// ============================================================================
__global__ __launch_bounds__(128)
void k2_mix(const float* __restrict__ G) {
    const int bg = blockIdx.x;     // 0..3
    const int j  = blockIdx.y;     // 0..63
    const int tid = threadIdx.x;   // 128
    const int bl = tid >> 4;       // 0..7
    const int e  = tid & 15;
    const float* Gje  = G + (size_t)j * (FEAT * EIG * EIG) + e * EIG;
    const float* zrow = g_z + ((size_t)bg * 8 + bl) * (FEAT * EIG);
    ull acc0 = 0ULL, acc1 = 0ULL, acc2 = 0ULL, acc3 = 0ULL;
    #pragma unroll 8
    for (int i = 0; i < FEAT; i++) {
        const ulonglong2* gp = (const ulonglong2*)(Gje + (size_t)i * (EIG * EIG));
        const ulonglong2* zq = (const ulonglong2*)(zrow + i * EIG);
        ulonglong2 g0 = gp[0], g1 = gp[1], g2 = gp[2], g3 = gp[3];
        ulonglong2 z0 = zq[0], z1 = zq[1], z2 = zq[2], z3 = zq[3];
        acc0 = ffma2(g0.x, z0.x, acc0);
        acc1 = ffma2(g0.y, z0.y, acc1);
        acc2 = ffma2(g1.x, z1.x, acc2);
        acc3 = ffma2(g1.y, z1.y, acc3);
        acc0 = ffma2(g2.x, z2.x, acc0);
        acc1 = ffma2(g2.y, z2.y, acc1);
        acc2 = ffma2(g3.x, z3.x, acc2);
        acc3 = ffma2(g3.y, z3.y, acc3);
    }
    float2 f0 = unpack2(acc0), f1 = unpack2(acc1);
    float2 f2 = unpack2(acc2), f3 = unpack2(acc3);
    g_w[((size_t)bg * 8 + bl) * (NOUT * EIG) + j * EIG + e] =
        ((f0.x + f0.y) + (f1.x + f1.y)) + ((f2.x + f2.y) + (f3.x + f3.y));
}

// ============================================================================
// Stage 3: out[b,n,j] = sum_e V[n,e] * w[b,j,e]   (R11/R12 verbatim: ~41us)
// ============================================================================
__global__ __launch_bounds__(256)
void k3_expand(const float* __restrict__ V, float* __restrict__ out) {
    __shared__ __align__(16) float vs[TN3 * EIG];        // 8 KB
    __shared__ __align__(16) float wsT[2][EIG * 65];     // 8.3 KB padded transpose
    const int b0 = blockIdx.y * 2;
    const int n0 = blockIdx.x * TN3;
    const int Nloc = (NODES - n0 < TN3) ? (NODES - n0) : TN3;   // 128 or 32
    const int tid = threadIdx.x;
    const int jp = tid & 31, nb = tid >> 5;

    #pragma unroll
    for (int bb = 0; bb < 2; bb++) {
        float4 fw = ((const float4*)(g_w + (size_t)(b0 + bb) * NOUT * EIG))[tid];
        int j = tid >> 2, e0 = (tid & 3) * 4;
        wsT[bb][(e0 + 0) * 65 + j] = fw.x;
        wsT[bb][(e0 + 1) * 65 + j] = fw.y;
        wsT[bb][(e0 + 2) * 65 + j] = fw.z;
        wsT[bb][(e0 + 3) * 65 + j] = fw.w;
    }
    {
        const float4* src = (const float4*)(V + (size_t)n0 * EIG);
        for (int idx = tid; idx < Nloc * 4; idx += 256) ((float4*)vs)[idx] = src[idx];
    }
    __syncthreads();

    ull wA0[8], wA1[8], wB0[8], wB1[8];
    #pragma unroll
    for (int k = 0; k < 8; k++) {
        wA0[k] = pack2(wsT[0][(2*k)*65 + 2*jp],     wsT[0][(2*k+1)*65 + 2*jp]);
        wA1[k] = pack2(wsT[0][(2*k)*65 + 2*jp + 1], wsT[0][(2*k+1)*65 + 2*jp + 1]);
        wB0[k] = pack2(wsT[1][(2*k)*65 + 2*jp],     wsT[1][(2*k+1)*65 + 2*jp]);
        wB1[k] = pack2(wsT[1][(2*k)*65 + 2*jp + 1], wsT[1][(2*k+1)*65 + 2*jp + 1]);
    }

    float* obA = out + (size_t)(b0)     * NODES * NOUT + (size_t)n0 * NOUT + 2 * jp;
    float* obB = out + (size_t)(b0 + 1) * NODES * NOUT + (size_t)n0 * NOUT + 2 * jp;

    #pragma unroll 4
    for (int t = 0; t < 16; t++) {
        const int n = nb * 16 + t;               // warp-uniform
        if (n >= Nloc) break;
        const ulonglong2* vp = (const ulonglong2*)(vs + n * EIG);
        ulonglong2 va = vp[0], vb = vp[1];
        ull aA0 = 0, aA1 = 0, aB0 = 0, aB1 = 0;
        aA0 = ffma2(va.x, wA0[0], aA0);  aA1 = ffma2(va.x, wA1[0], aA1);
        aB0 = ffma2(va.x, wB0[0], aB0);  aB1 = ffma2(va.x, wB1[0], aB1);
        aA0 = ffma2(va.y, wA0[1], aA0);  aA1 = ffma2(va.y, wA1[1], aA1);
        aB0 = ffma2(va.y, wB0[1], aB0);  aB1 = ffma2(va.y, wB1[1], aB1);
        aA0 = ffma2(vb.x, wA0[2], aA0);  aA1 = ffma2(vb.x, wA1[2], aA1);
        aB0 = ffma2(vb.x, wB0[2], aB0);  aB1 = ffma2(vb.x, wB1[2], aB1);
        aA0 = ffma2(vb.y, wA0[3], aA0);  aA1 = ffma2(vb.y, wA1[3], aA1);
        aB0 = ffma2(vb.y, wB0[3], aB0);  aB1 = ffma2(vb.y, wB1[3], aB1);
        ulonglong2 vc = vp[2], vd = vp[3];
        aA0 = ffma2(vc.x, wA0[4], aA0);  aA1 = ffma2(vc.x, wA1[4], aA1);
        aB0 = ffma2(vc.x, wB0[4], aB0);  aB1 = ffma2(vc.x, wB1[4], aB1);
        aA0 = ffma2(vc.y, wA0[5], aA0);  aA1 = ffma2(vc.y, wA1[5], aA1);
        aB0 = ffma2(vc.y, wB0[5], aB0);  aB1 = ffma2(vc.y, wB1[5], aB1);
        aA0 = ffma2(vd.x, wA0[6], aA0);  aA1 = ffma2(vd.x, wA1[6], aA1);
        aB0 = ffma2(vd.x, wB0[6], aB0);  aB1 = ffma2(vd.x, wB1[6], aB1);
        aA0 = ffma2(vd.y, wA0[7], aA0);  aA1 = ffma2(vd.y, wA1[7], aA1);
        aB0 = ffma2(vd.y, wB0[7], aB0);  aB1 = ffma2(vd.y, wB1[7], aB1);
        float2 rA0 = unpack2(aA0), rA1 = unpack2(aA1);
        float2 rB0 = unpack2(aB0), rB1 = unpack2(aB1);
        *(float2*)(obA + (size_t)n * NOUT) = make_float2(rA0.x + rA0.y, rA1.x + rA1.y);
        *(float2*)(obB + (size_t)n * NOUT) = make_float2(rB0.x + rB0.y, rB1.x + rB1.y);
    }
}

extern "C" void kernel_launch(void* const* d_in, const int* in_sizes, int n_in,
                              void* d_out, int out_size) {
    const float* x = (const float*)d_in[0];   // (32, 20000, 64) fp32
    const float* V = (const float*)d_in[1];   // (20000, 16)     fp32
    const float* G = (const float*)d_in[2];   // (64, 64, 16, 16) fp32
    float* out = (float*)d_out;               // (32, 20000, 64) fp32

    k1_project<<<dim3(NCHUNK, 16), 128>>>(x, V);
    k1_reduce<<<32, 256>>>();
    k2_mix<<<dim3(4, NOUT), 128>>>(G);
    k3_expand<<<dim3(NBLK3, BATCH / 2), 256>>>(V, out);
}

// round 17
// speedup vs baseline: 1.0982x; 1.0982x over previous
#include <cuda_runtime.h>
#include <cstdint>

#define NODES 20000
#define BATCH 32
#define FEAT  64
#define EIG   16
#define NOUT  64

// k1: 40 chunks x 512 nodes x 16 batch-pairs, 128 thr (R3/R4 skeleton + pair)
#define CHUNK1 512
#define NCHUNK 40
#define TM1    64           // panel nodes
// smem floats: xsA 4096 | xsB 4096 | vs 1024 = 9216 (36.9 KB)

// k3: 157 tiles x 128 nodes (last tile 32), 16 batch-pairs
#define TN3    128
#define NBLK3  157

typedef unsigned long long ull;

// Scratch (static device globals: allocation-free per harness rules)
// g_zpart[c][bp][bb][i][f]: 40*16*2048 floats = 5.24 MB
__device__ float g_zpart[(size_t)NCHUNK * 16 * 2048];
__device__ float g_z[BATCH * FEAT * EIG];                      // 128 KB
__device__ float g_w[BATCH * NOUT * EIG];                      // 128 KB

// ---- packed fp32x2 helpers (full-rate fp32 on sm_103a goes through FFMA2) ----
__device__ __forceinline__ ull pack2(float lo, float hi) {
    ull r; asm("mov.b64 %0, {%1, %2};" : "=l"(r) : "f"(lo), "f"(hi)); return r;
}
__device__ __forceinline__ float2 unpack2(ull v) {
    float2 r; asm("mov.b64 {%0, %1}, %2;" : "=f"(r.x), "=f"(r.y) : "l"(v)); return r;
}
__device__ __forceinline__ ull ffma2(ull a, ull b, ull c) {
    ull d; asm("fma.rn.f32x2 %0, %1, %2, %3;" : "=l"(d) : "l"(a), "l"(b), "l"(c)); return d;
}

// ============================================================================
// Stage 1: z[b,i,f] = sum_m V[m,f] * x[b,m,i]
// The MEASURED-BEST k1 skeleton (R3/R4, ~80us: 128 thr, x+V staged in smem,
// thread = 2i x 4f, EVERY warp walks every panel node -> no cross-warp
// reduction, direct-write epilogue) with ONE change: blockIdx.y = batch PAIR.
// A second x panel (xsB) is staged; the SAME warp-uniform V ulonglong2 load
// feeds both batches (k3's measured batch-pair amortization, R11 41.2us).
// Crossbar/node-batch: ~24 -> ~16 cyc. Accum 4 -> 8 ull; epilogue = proven
// direct float4 write, duplicated at +1024 for batch B. No new sync pattern.
// ============================================================================
__global__ __launch_bounds__(128)
void k1_project(const float* __restrict__ x, const float* __restrict__ V) {
    __shared__ __align__(16) float sm[9216];     // xsA | xsB | vs
    float* xsA = sm;
    float* xsB = sm + 4096;
    float* vs  = sm + 8192;
    const int c  = blockIdx.x;          // chunk 0..39
    const int bp = blockIdx.y;          // batch pair 0..15
    const int b0 = bp * 2;
    const int m0 = c * CHUNK1;
    const int tid = threadIdx.x;
    const int i2 = tid & 31;            // i-pair index: i = 2*i2, 2*i2+1
    const int fq = tid >> 5;            // f-quad: f = 4*fq .. 4*fq+3

    const float* xbA = x + ((size_t)b0 * NODES) * FEAT;
    const float* xbB = xbA + (size_t)NODES * FEAT;

    ull aA0 = 0, aA1 = 0, aA2 = 0, aA3 = 0;
    ull aB0 = 0, aB1 = 0, aB2 = 0, aB3 = 0;

    for (int t = 0; t < CHUNK1; t += TM1) {
        const int mb = m0 + t;
        // cooperative load: xA, xB panels (64 nodes x 64 feat; zero-fill OOB)
        #pragma unroll
        for (int r = 0; r < 8; r++) {
            int idx = r * 128 + tid;          // [0,1024) float4 slots
            int mm = idx >> 4, c4 = idx & 15;
            float4 vA = make_float4(0.f, 0.f, 0.f, 0.f);
            float4 vB = make_float4(0.f, 0.f, 0.f, 0.f);
            if (mb + mm < NODES) {
                vA = *(const float4*)(xbA + (size_t)(mb + mm) * FEAT + c4 * 4);
                vB = *(const float4*)(xbB + (size_t)(mb + mm) * FEAT + c4 * 4);
            }
            *(float4*)(xsA + mm * FEAT + c4 * 4) = vA;
            *(float4*)(xsB + mm * FEAT + c4 * 4) = vB;
        }
        // cooperative load: V panel (64 nodes x 16 eig; zero-fill OOB)
        #pragma unroll
        for (int r = 0; r < 2; r++) {
            int idx = r * 128 + tid;          // [0,256)
            int mm = idx >> 2, c4 = idx & 3;
            float4 v = make_float4(0.f, 0.f, 0.f, 0.f);
            if (mb + mm < NODES)
                v = *(const float4*)(V + (size_t)(mb + mm) * EIG + c4 * 4);
            *(float4*)(vs + mm * EIG + c4 * 4) = v;
        }
        __syncthreads();
        #pragma unroll 8
        for (int m = 0; m < TM1; m++) {
            float2 xa = *(const float2*)(xsA + m * FEAT + i2 * 2);
            float2 xb = *(const float2*)(xsB + m * FEAT + i2 * 2);
            ulonglong2 vv = *(const ulonglong2*)(vs + m * EIG + fq * 4);
            ull xa0 = pack2(xa.x, xa.x), xa1 = pack2(xa.y, xa.y);
            ull xb0 = pack2(xb.x, xb.x), xb1 = pack2(xb.y, xb.y);
            aA0 = ffma2(xa0, vv.x, aA0);
            aA1 = ffma2(xa0, vv.y, aA1);
            aA2 = ffma2(xa1, vv.x, aA2);
            aA3 = ffma2(xa1, vv.y, aA3);
            aB0 = ffma2(xb0, vv.x, aB0);
            aB1 = ffma2(xb0, vv.y, aB1);
            aB2 = ffma2(xb1, vv.x, aB2);
            aB3 = ffma2(xb1, vv.y, aB3);
        }
        __syncthreads();
    }

    // direct-write epilogue (R3/R4-proven), batch A then B at +1024
    float* gz = g_zpart + ((size_t)c * 16 + bp) * 2048;
    {
        float2 l0 = unpack2(aA0), h0 = unpack2(aA1);
        float2 l1 = unpack2(aA2), h1 = unpack2(aA3);
        *(float4*)(gz + (2 * i2) * EIG + fq * 4)     = make_float4(l0.x, l0.y, h0.x, h0.y);
        *(float4*)(gz + (2 * i2 + 1) * EIG + fq * 4) = make_float4(l1.x, l1.y, h1.x, h1.y);
    }
    {
        float2 l0 = unpack2(aB0), h0 = unpack2(aB1);
        float2 l1 = unpack2(aB2), h1 = unpack2(aB3);
        *(float4*)(gz + 1024 + (2 * i2) * EIG + fq * 4)     = make_float4(l0.x, l0.y, h0.x, h0.y);
        *(float4*)(gz + 1024 + (2 * i2 + 1) * EIG + fq * 4) = make_float4(l1.x, l1.y, h1.x, h1.y);
    }
}

// ============================================================================
// Stage 1b: reduce partial z over 40 chunks (fixed order -> deterministic)
// g_zpart inner layout [bp][bb][i][f] == g_z's [b][i][f] (validated in R16).
// ============================================================================
__global__ __launch_bounds__(256)
void k1_reduce() {
    const int q = blockIdx.x * 256 + threadIdx.x;   // over 8192 float4
    const float4* zp = (const float4*)g_zpart;
    float4 s = make_float4(0.f, 0.f, 0.f, 0.f);
    #pragma unroll 8
    for (int c = 0; c < NCHUNK; c++) {
        float4 v = zp[(size_t)c * 8192 + q];
        s.x += v.x; s.y += v.y; s.z += v.z; s.w += v.w;
    }
    ((float4*)g_z)[q] = s;
}

// ============================================================================
// Stage 2: w[b,j,e] = sum_{i,f} G[j,i,e,f] * z[b,i,f]  (verbatim)
// ============================================================================
__global__ __launch_bounds__(128)
void k2_mix(const float* __restrict__ G) {
    const int bg = blockIdx.x;     // 0..3
    const int j  = blockIdx.y;     // 0..63
    const int tid = threadIdx.x;   // 128
    const int bl = tid >> 4;       // 0..7
    const int e  = tid & 15;
    const float* Gje  = G + (size_t)j * (FEAT * EIG * EIG) + e * EIG;
    const float* zrow = g_z + ((size_t)bg * 8 + bl) * (FEAT * EIG);
    ull acc0 = 0ULL, acc1 = 0ULL, acc2 = 0ULL, acc3 = 0ULL;
    #pragma unroll 8
    for (int i = 0; i < FEAT; i++) {
        const ulonglong2* gp = (const ulonglong2*)(Gje + (size_t)i * (EIG * EIG));
        const ulonglong2* zq = (const ulonglong2*)(zrow + i * EIG);
        ulonglong2 g0 = gp[0], g1 = gp[1], g2 = gp[2], g3 = gp[3];
        ulonglong2 z0 = zq[0], z1 = zq[1], z2 = zq[2], z3 = zq[3];
        acc0 = ffma2(g0.x, z0.x, acc0);
        acc1 = ffma2(g0.y, z0.y, acc1);
        acc2 = ffma2(g1.x, z1.x, acc2);
        acc3 = ffma2(g1.y, z1.y, acc3);
        acc0 = ffma2(g2.x, z2.x, acc0);
        acc1 = ffma2(g2.y, z2.y, acc1);
        acc2 = ffma2(g3.x, z3.x, acc2);
        acc3 = ffma2(g3.y, z3.y, acc3);
    }
    float2 f0 = unpack2(acc0), f1 = unpack2(acc1);
    float2 f2 = unpack2(acc2), f3 = unpack2(acc3);
    g_w[((size_t)bg * 8 + bl) * (NOUT * EIG) + j * EIG + e] =
        ((f0.x + f0.y) + (f1.x + f1.y)) + ((f2.x + f2.y) + (f3.x + f3.y));
}

// ============================================================================
// Stage 3: out[b,n,j] = sum_e V[n,e] * w[b,j,e]  (R11 verbatim: 41.2us,
// reproduced 5x)
// ============================================================================
__global__ __launch_bounds__(256)
void k3_expand(const float* __restrict__ V, float* __restrict__ out) {
    __shared__ __align__(16) float vs[TN3 * EIG];        // 8 KB
    __shared__ __align__(16) float wsT[2][EIG * 65];     // 8.3 KB padded transpose
    const int b0 = blockIdx.y * 2;
    const int n0 = blockIdx.x * TN3;
    const int Nloc = (NODES - n0 < TN3) ? (NODES - n0) : TN3;   // 128 or 32
    const int tid = threadIdx.x;
    const int jp = tid & 31, nb = tid >> 5;

    #pragma unroll
    for (int bb = 0; bb < 2; bb++) {
        float4 fw = ((const float4*)(g_w + (size_t)(b0 + bb) * NOUT * EIG))[tid];
        int j = tid >> 2, e0 = (tid & 3) * 4;
        wsT[bb][(e0 + 0) * 65 + j] = fw.x;
        wsT[bb][(e0 + 1) * 65 + j] = fw.y;
        wsT[bb][(e0 + 2) * 65 + j] = fw.z;
        wsT[bb][(e0 + 3) * 65 + j] = fw.w;
    }
    {
        const float4* src = (const float4*)(V + (size_t)n0 * EIG);
        for (int idx = tid; idx < Nloc * 4; idx += 256) ((float4*)vs)[idx] = src[idx];
    }
    __syncthreads();

    ull wA0[8], wA1[8], wB0[8], wB1[8];
    #pragma unroll
    for (int k = 0; k < 8; k++) {
        wA0[k] = pack2(wsT[0][(2*k)*65 + 2*jp],     wsT[0][(2*k+1)*65 + 2*jp]);
        wA1[k] = pack2(wsT[0][(2*k)*65 + 2*jp + 1], wsT[0][(2*k+1)*65 + 2*jp + 1]);
        wB0[k] = pack2(wsT[1][(2*k)*65 + 2*jp],     wsT[1][(2*k+1)*65 + 2*jp]);
        wB1[k] = pack2(wsT[1][(2*k)*65 + 2*jp + 1], wsT[1][(2*k+1)*65 + 2*jp + 1]);
    }

    float* obA = out + (size_t)(b0)     * NODES * NOUT + (size_t)n0 * NOUT + 2 * jp;
    float* obB = out + (size_t)(b0 + 1) * NODES * NOUT + (size_t)n0 * NOUT + 2 * jp;

    #pragma unroll 4
    for (int t = 0; t < 16; t++) {
        const int n = nb * 16 + t;               // warp-uniform
        if (n >= Nloc) break;
        const ulonglong2* vp = (const ulonglong2*)(vs + n * EIG);
        ulonglong2 va = vp[0], vb = vp[1];
        ull aA0 = 0, aA1 = 0, aB0 = 0, aB1 = 0;
        aA0 = ffma2(va.x, wA0[0], aA0);  aA1 = ffma2(va.x, wA1[0], aA1);
        aB0 = ffma2(va.x, wB0[0], aB0);  aB1 = ffma2(va.x, wB1[0], aB1);
        aA0 = ffma2(va.y, wA0[1], aA0);  aA1 = ffma2(va.y, wA1[1], aA1);
        aB0 = ffma2(va.y, wB0[1], aB0);  aB1 = ffma2(va.y, wB1[1], aB1);
        aA0 = ffma2(vb.x, wA0[2], aA0);  aA1 = ffma2(vb.x, wA1[2], aA1);
        aB0 = ffma2(vb.x, wB0[2], aB0);  aB1 = ffma2(vb.x, wB1[2], aB1);
        aA0 = ffma2(vb.y, wA0[3], aA0);  aA1 = ffma2(vb.y, wA1[3], aA1);
        aB0 = ffma2(vb.y, wB0[3], aB0);  aB1 = ffma2(vb.y, wB1[3], aB1);
        ulonglong2 vc = vp[2], vd = vp[3];
        aA0 = ffma2(vc.x, wA0[4], aA0);  aA1 = ffma2(vc.x, wA1[4], aA1);
        aB0 = ffma2(vc.x, wB0[4], aB0);  aB1 = ffma2(vc.x, wB1[4], aB1);
        aA0 = ffma2(vc.y, wA0[5], aA0);  aA1 = ffma2(vc.y, wA1[5], aA1);
        aB0 = ffma2(vc.y, wB0[5], aB0);  aB1 = ffma2(vc.y, wB1[5], aB1);
        aA0 = ffma2(vd.x, wA0[6], aA0);  aA1 = ffma2(vd.x, wA1[6], aA1);
        aB0 = ffma2(vd.x, wB0[6], aB0);  aB1 = ffma2(vd.x, wB1[6], aB1);
        aA0 = ffma2(vd.y, wA0[7], aA0);  aA1 = ffma2(vd.y, wA1[7], aA1);
        aB0 = ffma2(vd.y, wB0[7], aB0);  aB1 = ffma2(vd.y, wB1[7], aB1);
        float2 rA0 = unpack2(aA0), rA1 = unpack2(aA1);
        float2 rB0 = unpack2(aB0), rB1 = unpack2(aB1);
        *(float2*)(obA + (size_t)n * NOUT) = make_float2(rA0.x + rA0.y, rA1.x + rA1.y);
        *(float2*)(obB + (size_t)n * NOUT) = make_float2(rB0.x + rB0.y, rB1.x + rB1.y);
    }
}

extern "C" void kernel_launch(void* const* d_in, const int* in_sizes, int n_in,
                              void* d_out, int out_size) {
    const float* x = (const float*)d_in[0];   // (32, 20000, 64) fp32
    const float* V = (const float*)d_in[1];   // (20000, 16)     fp32
    const float* G = (const float*)d_in[2];   // (64, 64, 16, 16) fp32
    float* out = (float*)d_out;               // (32, 20000, 64) fp32

    k1_project<<<dim3(NCHUNK, 16), 128>>>(x, V);
    k1_reduce<<<32, 256>>>();
    k2_mix<<<dim3(4, NOUT), 128>>>(G);
    k3_expand<<<dim3(NBLK3, BATCH / 2), 256>>>(V, out);
}